// round 13
// baseline (speedup 1.0000x reference)
#include <cuda_runtime.h>
#include <cuda_fp16.h>
#include <mma.h>

using namespace nvcuda;

#define N_NODES 50000
#define N_EDGES 800000
#define E2      850000   // edges + self loops
#define IN_F    128
#define HID     64
#define BN_EPS  1e-5f
#define INV_Nf  (1.0f / 50000.0f)

// ---------------- scratch (device globals; no allocation allowed) ----------------
__device__ int    g_is64;
__device__ int    g_deg[N_NODES];
__device__ int    g_fill[N_NODES];
__device__ float  g_dinv[N_NODES];
__device__ int    g_rowptr[N_NODES + 1];
__device__ __align__(16) int2 g_cw[E2 + 4];  // {col, weight-bits}; padded for int4 tail
__device__ __half g_hA[N_NODES * HID];
__device__ __half g_hB[N_NODES * HID];
__device__ __half g_h0[N_NODES * HID];
__device__ float  g_sumf[4][HID];
__device__ float  g_sqf[4][HID];

// ---------------- init: deg=1, fill=0, zero stats, detect edge dtype ----------------
__global__ void init_kernel(const int* __restrict__ e) {
    int n = blockIdx.x * blockDim.x + threadIdx.x;
    if (n < N_NODES) { g_deg[n] = 1; g_fill[n] = 0; }
    if (blockIdx.x == 0) {
        int t = threadIdx.x;
        if (t < 4 * HID) { ((float*)g_sumf)[t] = 0.f; ((float*)g_sqf)[t] = 0.f; }
        if (t < 32) {
            // int64 little-endian with values < 50000 -> odd 32-bit words all zero
            int nz = 0;
            #pragma unroll
            for (int i = 0; i < 4; i++) nz += (e[2 * (t * 4 + i) + 1] != 0);
            unsigned any = __any_sync(0xffffffffu, nz != 0);
            if (t == 0) g_is64 = any ? 0 : 1;
        }
    }
}

__device__ __forceinline__ int fetch_idx(const void* ei, long long pos) {
    int v;
    if (g_is64) v = (int)((const long long*)ei)[pos];
    else        v = ((const int*)ei)[pos];
    return min(max(v, 0), N_NODES - 1);   // crash insurance
}

__global__ void count_deg_kernel(const void* __restrict__ ei) {
    int e = blockIdx.x * blockDim.x + threadIdx.x;
    if (e < N_EDGES) atomicAdd(&g_deg[fetch_idx(ei, (long long)N_EDGES + e)], 1);
}

// single-block COALESCED scan: 32 warps, lane-strided loads, shfl scans; also writes dinv
__global__ void scan_kernel() {
    __shared__ int wsum[32], woff[32];
    const int REG = (N_NODES + 31) / 32;     // 1563 per warp region
    int wid  = threadIdx.x >> 5;
    int lane = threadIdx.x & 31;
    int base = wid * REG;
    int tot = 0;
    for (int i = 0; i < REG; i += 32) {
        int off = i + lane;
        int idx = base + off;
        int d = 0;
        if (off < REG && idx < N_NODES) {
            d = g_deg[idx];
            g_dinv[idx] = rsqrtf((float)d);
        }
        tot += d;
    }
    for (int o = 16; o; o >>= 1) tot += __shfl_xor_sync(0xffffffffu, tot, o);
    if (lane == 0) wsum[wid] = tot;
    __syncthreads();
    if (threadIdx.x < 32) {
        int v  = wsum[threadIdx.x];
        int ex = v;
        for (int o = 1; o < 32; o <<= 1) {
            int nb = __shfl_up_sync(0xffffffffu, ex, o);
            if (lane >= o) ex += nb;
        }
        woff[threadIdx.x] = ex - v;           // exclusive region offset
        if (threadIdx.x == 31) g_rowptr[N_NODES] = ex;
    }
    __syncthreads();
    int run = woff[wid];
    for (int i = 0; i < REG; i += 32) {
        int off = i + lane;
        int idx = base + off;
        bool ok = (off < REG) && (idx < N_NODES);
        int d = ok ? g_deg[idx] : 0;
        int ex = d;
        for (int o = 1; o < 32; o <<= 1) {
            int nb = __shfl_up_sync(0xffffffffu, ex, o);
            if (lane >= o) ex += nb;
        }
        int rowtot = __shfl_sync(0xffffffffu, ex, 31);
        ex -= d;                               // exclusive within row
        if (ok) g_rowptr[idx] = run + ex;
        run += rowtot;
    }
}

__global__ void fill_csr_kernel(const void* __restrict__ ei) {
    int e = blockIdx.x * blockDim.x + threadIdx.x;
    if (e >= E2) return;
    int s, d;
    if (e < N_EDGES) {
        s = fetch_idx(ei, e);
        d = fetch_idx(ei, (long long)N_EDGES + e);
    } else {
        s = e - N_EDGES; d = s;
    }
    int pos = g_rowptr[d] + atomicAdd(&g_fill[d], 1);
    g_cw[pos] = make_int2(s, __float_as_int(g_dinv[s] * g_dinv[d]));
}

// ---------------- SpMM (fp16 h): warp per 4 CONSECUTIVE nodes ----------------
// One coalesced rowptr fetch covers all 4 boundaries; metadata span contiguous (L1-resident);
// startup latency amortized 4x. Inner 8-wide loop is the proven R9/R12 form.
template <bool STATS>
__global__ __launch_bounds__(256) void spmm_kernel(
    const __half* __restrict__ hin, __half* __restrict__ hout,
    const float* __restrict__ bias, const __half* __restrict__ h0p,
    float wacc, float wh0, int set)
{
    __shared__ float ss[STATS ? 8 : 1][STATS ? HID : 1];
    __shared__ float qq[STATS ? 8 : 1][STATS ? HID : 1];
    int warp = threadIdx.x >> 5;
    int lane = threadIdx.x & 31;
    int n0   = (blockIdx.x * 8 + warp) * 4;
    const __half2* __restrict__ hin2 = (const __half2*)hin;
    const int4*    __restrict__ cw4  = (const int4*)g_cw;
    // one coalesced transaction covers boundaries for all 4 nodes
    int rp = 0;
    if (lane < 5) rp = g_rowptr[min(n0 + lane, N_NODES)];
    int b0 = __shfl_sync(0xffffffffu, rp, 0);
    int b1 = __shfl_sync(0xffffffffu, rp, 1);
    int b2 = __shfl_sync(0xffffffffu, rp, 2);
    int b3 = __shfl_sync(0xffffffffu, rp, 3);
    int b4 = __shfl_sync(0xffffffffu, rp, 4);
    float2 bval = make_float2(0.f, 0.f);
    if (bias) bval = ((const float2*)bias)[lane];
    float2 sacc = make_float2(0.f, 0.f), qacc = sacc;

#pragma unroll
    for (int k = 0; k < 4; k++) {
        int node = n0 + k;
        if (node >= N_NODES) break;
        int beg = (k == 0) ? b0 : (k == 1) ? b1 : (k == 2) ? b2 : b3;
        int end = (k == 0) ? b1 : (k == 1) ? b2 : (k == 2) ? b3 : b4;
        float2 a0 = make_float2(0.f, 0.f), a1 = a0, a2 = a0, a3 = a0;
        int e = beg;
        if ((e & 1) && e < end) {             // peel to 16B alignment of metadata
            int2 cw = g_cw[e];
            float w = __int_as_float(cw.y);
            float2 v = __half22float2(hin2[cw.x*32 + lane]);
            a0.x += w*v.x; a0.y += w*v.y;
            e++;
        }
        for (; e + 7 < end; e += 8) {
            int4 q0 = cw4[e >> 1];
            int4 q1 = cw4[(e >> 1) + 1];
            int4 q2 = cw4[(e >> 1) + 2];
            int4 q3 = cw4[(e >> 1) + 3];
            float2 v0 = __half22float2(hin2[q0.x*32 + lane]);
            float2 v1 = __half22float2(hin2[q0.z*32 + lane]);
            float2 v2 = __half22float2(hin2[q1.x*32 + lane]);
            float2 v3 = __half22float2(hin2[q1.z*32 + lane]);
            float2 v4 = __half22float2(hin2[q2.x*32 + lane]);
            float2 v5 = __half22float2(hin2[q2.z*32 + lane]);
            float2 v6 = __half22float2(hin2[q3.x*32 + lane]);
            float2 v7 = __half22float2(hin2[q3.z*32 + lane]);
            float w0 = __int_as_float(q0.y), w1 = __int_as_float(q0.w);
            float w2 = __int_as_float(q1.y), w3 = __int_as_float(q1.w);
            float w4 = __int_as_float(q2.y), w5 = __int_as_float(q2.w);
            float w6 = __int_as_float(q3.y), w7 = __int_as_float(q3.w);
            a0.x += w0*v0.x; a0.y += w0*v0.y;
            a1.x += w1*v1.x; a1.y += w1*v1.y;
            a2.x += w2*v2.x; a2.y += w2*v2.y;
            a3.x += w3*v3.x; a3.y += w3*v3.y;
            a0.x += w4*v4.x; a0.y += w4*v4.y;
            a1.x += w5*v5.x; a1.y += w5*v5.y;
            a2.x += w6*v6.x; a2.y += w6*v6.y;
            a3.x += w7*v7.x; a3.y += w7*v7.y;
        }
        for (; e + 1 < end; e += 2) {
            int4 q0 = cw4[e >> 1];
            float2 v0 = __half22float2(hin2[q0.x*32 + lane]);
            float2 v1 = __half22float2(hin2[q0.z*32 + lane]);
            float w0 = __int_as_float(q0.y), w1 = __int_as_float(q0.w);
            a0.x += w0*v0.x; a0.y += w0*v0.y;
            a1.x += w1*v1.x; a1.y += w1*v1.y;
        }
        if (e < end) {
            int2 cw = g_cw[e];
            float w = __int_as_float(cw.y);
            float2 v = __half22float2(hin2[cw.x*32 + lane]);
            a0.x += w*v.x; a0.y += w*v.y;
        }
        float2 r;
        r.x = ((a0.x + a1.x) + (a2.x + a3.x)) * wacc + bval.x;
        r.y = ((a0.y + a1.y) + (a2.y + a3.y)) * wacc + bval.y;
        if (h0p) {
            float2 z = __half22float2(((const __half2*)h0p)[node*32 + lane]);
            r.x += wh0 * z.x; r.y += wh0 * z.y;
        }
        ((__half2*)hout)[node*32 + lane] = __floats2half2_rn(r.x, r.y);
        if (STATS) {
            sacc.x += r.x;       sacc.y += r.y;
            qacc.x += r.x * r.x; qacc.y += r.y * r.y;
        }
    }
    if (STATS) {
        ss[warp][2*lane]     = sacc.x;
        ss[warp][2*lane + 1] = sacc.y;
        qq[warp][2*lane]     = qacc.x;
        qq[warp][2*lane + 1] = qacc.y;
        __syncthreads();
        int t = threadIdx.x;
        if (t < HID) {
            float s = 0.f;
#pragma unroll
            for (int g = 0; g < 8; g++) s += ss[g][t];
            atomicAdd(&g_sumf[set][t], s);
        } else if (t < 2 * HID) {
            float q = 0.f;
#pragma unroll
            for (int g = 0; g < 8; g++) q += qq[g][t - HID];
            atomicAdd(&g_sqf[set][t - HID], q);
        }
    }
}

// ---------------- tensor-core GEMM: block = 128 nodes x 64 features, wmma 16x16x16 ----------------
template <int KIN, int BNSET, typename TA>
__global__ __launch_bounds__(256) void gemm_mma_kernel(
    const TA* __restrict__ A, const float* __restrict__ W,
    const float* __restrict__ bias, __half* __restrict__ C,
    const float* __restrict__ gam, const float* __restrict__ bet)
{
    struct Stage { __half As[128][72]; __half Ws[64][72]; };
    __shared__ union U { Stage st; float Cs[128][68]; U(){} } SM;
    __shared__ float sc[HID], sh[HID];
    int tid  = threadIdx.x;
    int warp = tid >> 5;
    if (BNSET >= 0) {
        if (tid < HID) {
            float mean = g_sumf[BNSET][tid] * INV_Nf;
            float var  = g_sqf[BNSET][tid] * INV_Nf - mean * mean;
            float s = gam[tid] * rsqrtf(var + BN_EPS);
            sc[tid] = s;
            sh[tid] = bet[tid] - mean * s;
        }
        __syncthreads();
    }
    int base = blockIdx.x * 128;
    wmma::fragment<wmma::accumulator, 16, 16, 16, float> acc[4];
#pragma unroll
    for (int i = 0; i < 4; i++) wmma::fill_fragment(acc[i], 0.f);

    for (int k0 = 0; k0 < KIN; k0 += 64) {
        __syncthreads();
        for (int i = tid; i < 128 * 32; i += 256) {
            int r = i >> 5, c = (i & 31) * 2;
            float v0 = 0.f, v1 = 0.f;
            if (base + r < N_NODES) {
                if constexpr (sizeof(TA) == 2) {
                    float2 p = __half22float2(((const __half2*)A)[((base + r) * KIN + k0 + c) >> 1]);
                    v0 = p.x; v1 = p.y;
                } else {
                    float2 p = ((const float2*)A)[((base + r) * KIN + k0 + c) >> 1];
                    v0 = p.x; v1 = p.y;
                }
            }
            if (BNSET >= 0) {
                v0 = fmaxf(fmaf(v0, sc[k0 + c],     sh[k0 + c]),     0.f);
                v1 = fmaxf(fmaf(v1, sc[k0 + c + 1], sh[k0 + c + 1]), 0.f);
            }
            *reinterpret_cast<__half2*>(&SM.st.As[r][c]) = __floats2half2_rn(v0, v1);
        }
        for (int i = tid; i < 64 * 32; i += 256) {
            int k = i >> 5, n = (i & 31) * 2;
            float2 p = ((const float2*)W)[((k0 + k) * 64 + n) >> 1];
            *reinterpret_cast<__half2*>(&SM.st.Ws[k][n]) = __floats2half2_rn(p.x, p.y);
        }
        __syncthreads();
        int r0 = warp * 16;
#pragma unroll
        for (int kk = 0; kk < 64; kk += 16) {
            wmma::fragment<wmma::matrix_a, 16, 16, 16, __half, wmma::row_major> af;
            wmma::load_matrix_sync(af, &SM.st.As[r0][kk], 72);
#pragma unroll
            for (int nt = 0; nt < 4; nt++) {
                wmma::fragment<wmma::matrix_b, 16, 16, 16, __half, wmma::row_major> bf;
                wmma::load_matrix_sync(bf, &SM.st.Ws[kk][nt * 16], 72);
                wmma::mma_sync(acc[nt], af, bf, acc[nt]);
            }
        }
    }
    __syncthreads();   // As/Ws dead; Cs aliases them
#pragma unroll
    for (int nt = 0; nt < 4; nt++)
        wmma::store_matrix_sync(&SM.Cs[warp * 16][nt * 16], acc[nt], 68, wmma::mem_row_major);
    __syncthreads();
    for (int i = tid; i < 128 * 32; i += 256) {
        int r = i >> 5, c = (i & 31) * 2;
        int node = base + r;
        if (node < N_NODES) {
            float b0 = bias ? bias[c]     : 0.f;
            float b1 = bias ? bias[c + 1] : 0.f;
            ((__half2*)C)[(node * 64 + c) >> 1] =
                __floats2half2_rn(SM.Cs[r][c] + b0, SM.Cs[r][c + 1] + b1);
        }
    }
}

// ---------------- layer-4 BN apply (inline finalize) -> writes h and h0 (fp16) ----------------
__global__ __launch_bounds__(256) void bn_apply_final_kernel(
    __half* __restrict__ h, __half* __restrict__ h0,
    const float* __restrict__ gam, const float* __restrict__ bet)
{
    __shared__ float sc[HID], sh[HID];
    int tid = threadIdx.x;
    if (tid < HID) {
        float mean = g_sumf[3][tid] * INV_Nf;
        float var  = g_sqf[3][tid] * INV_Nf - mean * mean;
        float s = gam[tid] * rsqrtf(var + BN_EPS);
        sc[tid] = s;
        sh[tid] = bet[tid] - mean * s;
    }
    __syncthreads();
    int i = blockIdx.x * blockDim.x + tid;   // over N*32 half2s (exact)
    float2 v = __half22float2(((const __half2*)h)[i]);
    int f = (i * 2) & (HID - 1);
    v.x = fmaxf(fmaf(v.x, sc[f],     sh[f]),     0.f);
    v.y = fmaxf(fmaf(v.y, sc[f + 1], sh[f + 1]), 0.f);
    __half2 o = __floats2half2_rn(v.x, v.y);
    ((__half2*)h)[i]  = o;
    ((__half2*)h0)[i] = o;
}

// ---------------- fused FC + log-softmax: out = log_softmax(A @ Wfc + bfc) ----------------
__global__ __launch_bounds__(256) void fc_logsoftmax_kernel(
    const __half* __restrict__ A, const float* __restrict__ W,
    const float* __restrict__ bias, float* __restrict__ out)
{
    __shared__ float Ws[64 * 64];
    __shared__ float As[32 * 64];
    __shared__ float L[32][65];
    int tid = threadIdx.x;
    for (int i = tid; i < 64 * 64; i += 256) Ws[i] = W[i];
    int base = blockIdx.x * 32;
    for (int i = tid; i < 32 * 32; i += 256) {     // 32 rows x 32 half2
        int r = i / 32, c = (i - r * 32) * 2;
        float2 p = make_float2(0.f, 0.f);
        if (base + r < N_NODES)
            p = __half22float2(((const __half2*)A)[((base + r) * 64 + c) >> 1]);
        As[r * 64 + c]     = p.x;
        As[r * 64 + c + 1] = p.y;
    }
    __syncthreads();
    int f  = tid & 63;
    int ig = tid >> 6;
    float acc[8];
#pragma unroll
    for (int i = 0; i < 8; i++) acc[i] = 0.f;
#pragma unroll 8
    for (int k = 0; k < 64; k++) {
        float wv = Ws[k * 64 + f];
#pragma unroll
        for (int i = 0; i < 8; i++)
            acc[i] += As[(ig * 8 + i) * 64 + k] * wv;
    }
    float bv = bias[f];
#pragma unroll
    for (int i = 0; i < 8; i++) L[ig * 8 + i][f] = acc[i] + bv;
    __syncthreads();
    int w = tid >> 5, lane = tid & 31;
#pragma unroll
    for (int j = 0; j < 4; j++) {
        int r = w * 4 + j;
        int node = base + r;
        if (node >= N_NODES) break;
        float v0 = L[r][lane], v1 = L[r][lane + 32];
        float m = fmaxf(v0, v1);
        for (int o = 16; o; o >>= 1) m = fmaxf(m, __shfl_xor_sync(0xffffffffu, m, o));
        float s = __expf(v0 - m) + __expf(v1 - m);
        for (int o = 16; o; o >>= 1) s += __shfl_xor_sync(0xffffffffu, s, o);
        float ls = m + __logf(s);
        out[node * 64 + lane]      = v0 - ls;
        out[node * 64 + lane + 32] = v1 - ls;
    }
}

// ---------------- host ----------------
extern "C" void kernel_launch(void* const* d_in, const int* in_sizes, int n_in,
                              void* d_out, int out_size) {
    const float* x   = (const float*)d_in[0];
    const void*  ei  = d_in[1];            // int32 or int64, detected on device
    const float* W1  = (const float*)d_in[2];
    const float* b1  = (const float*)d_in[3];
    const float* W2  = (const float*)d_in[4];
    const float* b2  = (const float*)d_in[5];
    const float* Wx  = (const float*)d_in[6];   // [2,64,64]
    const float* bx  = (const float*)d_in[7];   // [2,64]
    const float* g1  = (const float*)d_in[8];
    const float* be1 = (const float*)d_in[9];
    const float* g2  = (const float*)d_in[10];
    const float* be2 = (const float*)d_in[11];
    const float* g3  = (const float*)d_in[12];
    const float* be3 = (const float*)d_in[13];
    const float* Wfc = (const float*)d_in[14];
    const float* bfc = (const float*)d_in[15];
    float* out = (float*)d_out;

    __half *hA, *hB, *h0;
    cudaGetSymbolAddress((void**)&hA, g_hA);
    cudaGetSymbolAddress((void**)&hB, g_hB);
    cudaGetSymbolAddress((void**)&h0, g_h0);

    // ---- build normalized CSR (by dst) ----
    init_kernel<<<(N_NODES + 255) / 256, 256>>>((const int*)ei);
    count_deg_kernel<<<(N_EDGES + 255) / 256, 256>>>(ei);
    scan_kernel<<<1, 1024>>>();
    fill_csr_kernel<<<(E2 + 255) / 256, 256>>>(ei);

    const int GEMM_GRID = (N_NODES + 127) / 128;   // 391
    const int FC_GRID   = (N_NODES + 31) / 32;     // 1563
    const int SPMM_GRID = (N_NODES + 31) / 32;     // 1563 (8 warps x 4 nodes)

    // ---- layer 1 (IN_F=128 fp32 input, no BN) ----
    gemm_mma_kernel<128, -1, float><<<GEMM_GRID, 256>>>(x, W1, nullptr, hB, nullptr, nullptr);
    spmm_kernel<true><<<SPMM_GRID, 256>>>(hB, hA, b1, nullptr, 1.f, 0.f, 0);
    // ---- layer 2 (BN set 0 fused into GEMM input) ----
    gemm_mma_kernel<64, 0, __half><<<GEMM_GRID, 256>>>(hA, W2, nullptr, hB, g1, be1);
    spmm_kernel<true><<<SPMM_GRID, 256>>>(hB, hA, b2, nullptr, 1.f, 0.f, 1);
    // ---- extra layer 0 (BN set 1) ----
    gemm_mma_kernel<64, 1, __half><<<GEMM_GRID, 256>>>(hA, Wx, nullptr, hB, g2, be2);
    spmm_kernel<true><<<SPMM_GRID, 256>>>(hB, hA, bx, nullptr, 1.f, 0.f, 2);
    // ---- extra layer 1 (BN set 2) ----
    gemm_mma_kernel<64, 2, __half><<<GEMM_GRID, 256>>>(hA, Wx + 64 * 64, nullptr, hB, g3, be3);
    spmm_kernel<true><<<SPMM_GRID, 256>>>(hB, hA, bx + 64, nullptr, 1.f, 0.f, 3);
    // ---- final BN apply (set 3) -> hA normalized, h0 copy ----
    bn_apply_final_kernel<<<(N_NODES * 32) / 256, 256>>>(hA, h0, g3, be3);

    // ---- APPNP: 10 steps, ping-pong hA <-> hB ----
    __half* cur = hA;
    __half* nxt = hB;
    for (int it = 0; it < 10; it++) {
        spmm_kernel<false><<<SPMM_GRID, 256>>>(cur, nxt, nullptr, h0, 0.9f, 0.1f, 0);
        __half* t = cur; cur = nxt; nxt = t;
    }
    // result in hA

    // ---- head: FC + log_softmax fused ----
    fc_logsoftmax_kernel<<<FC_GRID, 256>>>(cur, Wfc, bfc, out);
}

// round 14
// speedup vs baseline: 1.1786x; 1.1786x over previous
#include <cuda_runtime.h>
#include <cuda_fp16.h>
#include <mma.h>

using namespace nvcuda;

#define N_NODES 50000
#define N_EDGES 800000
#define E2      850000   // edges + self loops
#define EPADMAX (E2 + N_NODES)   // worst-case even-padded CSR
#define IN_F    128
#define HID     64
#define BN_EPS  1e-5f
#define INV_Nf  (1.0f / 50000.0f)

// ---------------- scratch (device globals; no allocation allowed) ----------------
__device__ int    g_is64;
__device__ int    g_deg[N_NODES];
__device__ int    g_fill[N_NODES];        // seeded with rowptr by scan
__device__ float  g_dinv[N_NODES];
__device__ int    g_rowptr[N_NODES + 1];
__device__ __align__(16) int2 g_cw[EPADMAX + 4];  // {col, weight-bits}; rows even-padded
__device__ __half g_hA[N_NODES * HID];
__device__ __half g_hB[N_NODES * HID];
__device__ __half g_h0[N_NODES * HID];
__device__ float  g_sumf[4][HID];
__device__ float  g_sqf[4][HID];

// ---------------- init: deg=1, zero stats, detect edge dtype ----------------
__global__ void init_kernel(const int* __restrict__ e) {
    int n = blockIdx.x * blockDim.x + threadIdx.x;
    if (n < N_NODES) g_deg[n] = 1;        // self loop
    if (blockIdx.x == 0) {
        int t = threadIdx.x;
        if (t < 4 * HID) { ((float*)g_sumf)[t] = 0.f; ((float*)g_sqf)[t] = 0.f; }
        if (t < 32) {
            // int64 little-endian with values < 50000 -> odd 32-bit words all zero
            int nz = 0;
            #pragma unroll
            for (int i = 0; i < 4; i++) nz += (e[2 * (t * 4 + i) + 1] != 0);
            unsigned any = __any_sync(0xffffffffu, nz != 0);
            if (t == 0) g_is64 = any ? 0 : 1;
        }
    }
}

__device__ __forceinline__ int fetch_idx(const void* ei, long long pos) {
    int v;
    if (g_is64) v = (int)((const long long*)ei)[pos];
    else        v = ((const int*)ei)[pos];
    return min(max(v, 0), N_NODES - 1);   // crash insurance
}

__global__ void count_deg_kernel(const void* __restrict__ ei) {
    int e = blockIdx.x * blockDim.x + threadIdx.x;
    if (e < N_EDGES) atomicAdd(&g_deg[fetch_idx(ei, (long long)N_EDGES + e)], 1);
}

// single-block COALESCED scan over EVEN-PADDED degrees; writes dinv, rowptr,
// seeds g_fill = rowptr, and zero-fills each row's pad slot.
__global__ void scan_kernel() {
    __shared__ int wsum[32], woff[32];
    const int REG = (N_NODES + 31) / 32;     // 1563 per warp region
    int wid  = threadIdx.x >> 5;
    int lane = threadIdx.x & 31;
    int base = wid * REG;
    int tot = 0;
    for (int i = 0; i < REG; i += 32) {
        int off = i + lane;
        int idx = base + off;
        int d = 0;
        if (off < REG && idx < N_NODES) {
            int dg = g_deg[idx];
            g_dinv[idx] = rsqrtf((float)dg);
            d = dg + (dg & 1);               // even-padded length
        }
        tot += d;
    }
    for (int o = 16; o; o >>= 1) tot += __shfl_xor_sync(0xffffffffu, tot, o);
    if (lane == 0) wsum[wid] = tot;
    __syncthreads();
    if (threadIdx.x < 32) {
        int v  = wsum[threadIdx.x];
        int ex = v;
        for (int o = 1; o < 32; o <<= 1) {
            int nb = __shfl_up_sync(0xffffffffu, ex, o);
            if (lane >= o) ex += nb;
        }
        woff[threadIdx.x] = ex - v;           // exclusive region offset
        if (threadIdx.x == 31) g_rowptr[N_NODES] = ex;
    }
    __syncthreads();
    int run = woff[wid];
    for (int i = 0; i < REG; i += 32) {
        int off = i + lane;
        int idx = base + off;
        bool ok = (off < REG) && (idx < N_NODES);
        int dg = ok ? g_deg[idx] : 0;
        int d  = dg + (dg & 1);
        int ex = d;
        for (int o = 1; o < 32; o <<= 1) {
            int nb = __shfl_up_sync(0xffffffffu, ex, o);
            if (lane >= o) ex += nb;
        }
        int rowtot = __shfl_sync(0xffffffffu, ex, 31);
        ex -= d;                               // exclusive within row
        if (ok) {
            int rp = run + ex;
            g_rowptr[idx] = rp;
            g_fill[idx]   = rp;                // fill cursor starts at row base
            if (dg & 1) g_cw[rp + dg] = make_int2(0, 0);  // zero-weight pad slot
        }
        run += rowtot;
    }
}

__global__ void fill_csr_kernel(const void* __restrict__ ei) {
    int e = blockIdx.x * blockDim.x + threadIdx.x;
    if (e >= E2) return;
    int s, d;
    if (e < N_EDGES) {
        s = fetch_idx(ei, e);
        d = fetch_idx(ei, (long long)N_EDGES + e);
    } else {
        s = e - N_EDGES; d = s;
    }
    int pos = atomicAdd(&g_fill[d], 1);       // cursor pre-seeded with rowptr
    g_cw[pos] = make_int2(s, __float_as_int(g_dinv[s] * g_dinv[d]));
}

// ---------------- SpMM (fp16 h): R12 champion form — warp per node, 8-deep MLP ----------------
// Rows even-padded: no peel, no scalar tail.
template <bool STATS>
__global__ __launch_bounds__(256) void spmm_kernel(
    const __half* __restrict__ hin, __half* __restrict__ hout,
    const float* __restrict__ bias, const __half* __restrict__ h0p,
    float wacc, float wh0, int set)
{
    __shared__ float ss[STATS ? 8 : 1][STATS ? HID : 1];
    __shared__ float qq[STATS ? 8 : 1][STATS ? HID : 1];
    int warp = threadIdx.x >> 5;
    int node = blockIdx.x * 8 + warp;
    int lane = threadIdx.x & 31;
    const __half2* __restrict__ hin2 = (const __half2*)hin;
    const int4*    __restrict__ cw4  = (const int4*)g_cw;
    int beg = g_rowptr[node];
    int end = g_rowptr[node + 1];
    float2 a0 = make_float2(0.f, 0.f), a1 = a0, a2 = a0, a3 = a0;
    int e = beg;
    for (; e + 7 < end; e += 8) {
        int4 q0 = cw4[e >> 1];
        int4 q1 = cw4[(e >> 1) + 1];
        int4 q2 = cw4[(e >> 1) + 2];
        int4 q3 = cw4[(e >> 1) + 3];
        float2 v0 = __half22float2(hin2[q0.x*32 + lane]);
        float2 v1 = __half22float2(hin2[q0.z*32 + lane]);
        float2 v2 = __half22float2(hin2[q1.x*32 + lane]);
        float2 v3 = __half22float2(hin2[q1.z*32 + lane]);
        float2 v4 = __half22float2(hin2[q2.x*32 + lane]);
        float2 v5 = __half22float2(hin2[q2.z*32 + lane]);
        float2 v6 = __half22float2(hin2[q3.x*32 + lane]);
        float2 v7 = __half22float2(hin2[q3.z*32 + lane]);
        float w0 = __int_as_float(q0.y), w1 = __int_as_float(q0.w);
        float w2 = __int_as_float(q1.y), w3 = __int_as_float(q1.w);
        float w4 = __int_as_float(q2.y), w5 = __int_as_float(q2.w);
        float w6 = __int_as_float(q3.y), w7 = __int_as_float(q3.w);
        a0.x += w0*v0.x; a0.y += w0*v0.y;
        a1.x += w1*v1.x; a1.y += w1*v1.y;
        a2.x += w2*v2.x; a2.y += w2*v2.y;
        a3.x += w3*v3.x; a3.y += w3*v3.y;
        a0.x += w4*v4.x; a0.y += w4*v4.y;
        a1.x += w5*v5.x; a1.y += w5*v5.y;
        a2.x += w6*v6.x; a2.y += w6*v6.y;
        a3.x += w7*v7.x; a3.y += w7*v7.y;
    }
    for (; e < end; e += 2) {                 // even tail (rows are even-padded)
        int4 q0 = cw4[e >> 1];
        float2 v0 = __half22float2(hin2[q0.x*32 + lane]);
        float2 v1 = __half22float2(hin2[q0.z*32 + lane]);
        float w0 = __int_as_float(q0.y), w1 = __int_as_float(q0.w);
        a0.x += w0*v0.x; a0.y += w0*v0.y;
        a1.x += w1*v1.x; a1.y += w1*v1.y;
    }
    float2 r;
    r.x = ((a0.x + a1.x) + (a2.x + a3.x)) * wacc;
    r.y = ((a0.y + a1.y) + (a2.y + a3.y)) * wacc;
    if (bias) {
        float2 b = ((const float2*)bias)[lane];
        r.x += b.x; r.y += b.y;
    }
    if (h0p) {
        float2 z = __half22float2(((const __half2*)h0p)[node*32 + lane]);
        r.x += wh0 * z.x; r.y += wh0 * z.y;
    }
    ((__half2*)hout)[node*32 + lane] = __floats2half2_rn(r.x, r.y);
    if (STATS) {
        ss[warp][2*lane]     = r.x;
        ss[warp][2*lane + 1] = r.y;
        qq[warp][2*lane]     = r.x * r.x;
        qq[warp][2*lane + 1] = r.y * r.y;
        __syncthreads();
        int t = threadIdx.x;
        if (t < HID) {
            float s = 0.f;
#pragma unroll
            for (int g = 0; g < 8; g++) s += ss[g][t];
            atomicAdd(&g_sumf[set][t], s);
        } else if (t < 2 * HID) {
            float q = 0.f;
#pragma unroll
            for (int g = 0; g < 8; g++) q += qq[g][t - HID];
            atomicAdd(&g_sqf[set][t - HID], q);
        }
    }
}

// ---------------- tensor-core GEMM: block = 128 nodes x 64 features, wmma 16x16x16 ----------------
template <int KIN, int BNSET, typename TA>
__global__ __launch_bounds__(256) void gemm_mma_kernel(
    const TA* __restrict__ A, const float* __restrict__ W,
    const float* __restrict__ bias, __half* __restrict__ C,
    const float* __restrict__ gam, const float* __restrict__ bet)
{
    struct Stage { __half As[128][72]; __half Ws[64][72]; };
    __shared__ union U { Stage st; float Cs[128][68]; U(){} } SM;
    __shared__ float sc[HID], sh[HID];
    int tid  = threadIdx.x;
    int warp = tid >> 5;
    if (BNSET >= 0) {
        if (tid < HID) {
            float mean = g_sumf[BNSET][tid] * INV_Nf;
            float var  = g_sqf[BNSET][tid] * INV_Nf - mean * mean;
            float s = gam[tid] * rsqrtf(var + BN_EPS);
            sc[tid] = s;
            sh[tid] = bet[tid] - mean * s;
        }
        __syncthreads();
    }
    int base = blockIdx.x * 128;
    wmma::fragment<wmma::accumulator, 16, 16, 16, float> acc[4];
#pragma unroll
    for (int i = 0; i < 4; i++) wmma::fill_fragment(acc[i], 0.f);

    for (int k0 = 0; k0 < KIN; k0 += 64) {
        __syncthreads();
        for (int i = tid; i < 128 * 32; i += 256) {
            int r = i >> 5, c = (i & 31) * 2;
            float v0 = 0.f, v1 = 0.f;
            if (base + r < N_NODES) {
                if constexpr (sizeof(TA) == 2) {
                    float2 p = __half22float2(((const __half2*)A)[((base + r) * KIN + k0 + c) >> 1]);
                    v0 = p.x; v1 = p.y;
                } else {
                    float2 p = ((const float2*)A)[((base + r) * KIN + k0 + c) >> 1];
                    v0 = p.x; v1 = p.y;
                }
            }
            if (BNSET >= 0) {
                v0 = fmaxf(fmaf(v0, sc[k0 + c],     sh[k0 + c]),     0.f);
                v1 = fmaxf(fmaf(v1, sc[k0 + c + 1], sh[k0 + c + 1]), 0.f);
            }
            *reinterpret_cast<__half2*>(&SM.st.As[r][c]) = __floats2half2_rn(v0, v1);
        }
        for (int i = tid; i < 64 * 32; i += 256) {
            int k = i >> 5, n = (i & 31) * 2;
            float2 p = ((const float2*)W)[((k0 + k) * 64 + n) >> 1];
            *reinterpret_cast<__half2*>(&SM.st.Ws[k][n]) = __floats2half2_rn(p.x, p.y);
        }
        __syncthreads();
        int r0 = warp * 16;
#pragma unroll
        for (int kk = 0; kk < 64; kk += 16) {
            wmma::fragment<wmma::matrix_a, 16, 16, 16, __half, wmma::row_major> af;
            wmma::load_matrix_sync(af, &SM.st.As[r0][kk], 72);
#pragma unroll
            for (int nt = 0; nt < 4; nt++) {
                wmma::fragment<wmma::matrix_b, 16, 16, 16, __half, wmma::row_major> bf;
                wmma::load_matrix_sync(bf, &SM.st.Ws[kk][nt * 16], 72);
                wmma::mma_sync(acc[nt], af, bf, acc[nt]);
            }
        }
    }
    __syncthreads();   // As/Ws dead; Cs aliases them
#pragma unroll
    for (int nt = 0; nt < 4; nt++)
        wmma::store_matrix_sync(&SM.Cs[warp * 16][nt * 16], acc[nt], 68, wmma::mem_row_major);
    __syncthreads();
    for (int i = tid; i < 128 * 32; i += 256) {
        int r = i >> 5, c = (i & 31) * 2;
        int node = base + r;
        if (node < N_NODES) {
            float b0 = bias ? bias[c]     : 0.f;
            float b1 = bias ? bias[c + 1] : 0.f;
            ((__half2*)C)[(node * 64 + c) >> 1] =
                __floats2half2_rn(SM.Cs[r][c] + b0, SM.Cs[r][c + 1] + b1);
        }
    }
}

// ---------------- layer-4 BN apply (inline finalize) -> writes h and h0 (fp16) ----------------
__global__ __launch_bounds__(256) void bn_apply_final_kernel(
    __half* __restrict__ h, __half* __restrict__ h0,
    const float* __restrict__ gam, const float* __restrict__ bet)
{
    __shared__ float sc[HID], sh[HID];
    int tid = threadIdx.x;
    if (tid < HID) {
        float mean = g_sumf[3][tid] * INV_Nf;
        float var  = g_sqf[3][tid] * INV_Nf - mean * mean;
        float s = gam[tid] * rsqrtf(var + BN_EPS);
        sc[tid] = s;
        sh[tid] = bet[tid] - mean * s;
    }
    __syncthreads();
    int i = blockIdx.x * blockDim.x + tid;   // over N*32 half2s (exact)
    float2 v = __half22float2(((const __half2*)h)[i]);
    int f = (i * 2) & (HID - 1);
    v.x = fmaxf(fmaf(v.x, sc[f],     sh[f]),     0.f);
    v.y = fmaxf(fmaf(v.y, sc[f + 1], sh[f + 1]), 0.f);
    __half2 o = __floats2half2_rn(v.x, v.y);
    ((__half2*)h)[i]  = o;
    ((__half2*)h0)[i] = o;
}

// ---------------- fused FC + log-softmax: out = log_softmax(A @ Wfc + bfc) ----------------
__global__ __launch_bounds__(256) void fc_logsoftmax_kernel(
    const __half* __restrict__ A, const float* __restrict__ W,
    const float* __restrict__ bias, float* __restrict__ out)
{
    __shared__ float Ws[64 * 64];
    __shared__ float As[32 * 64];
    __shared__ float L[32][65];
    int tid = threadIdx.x;
    for (int i = tid; i < 64 * 64; i += 256) Ws[i] = W[i];
    int base = blockIdx.x * 32;
    for (int i = tid; i < 32 * 32; i += 256) {     // 32 rows x 32 half2
        int r = i / 32, c = (i - r * 32) * 2;
        float2 p = make_float2(0.f, 0.f);
        if (base + r < N_NODES)
            p = __half22float2(((const __half2*)A)[((base + r) * 64 + c) >> 1]);
        As[r * 64 + c]     = p.x;
        As[r * 64 + c + 1] = p.y;
    }
    __syncthreads();
    int f  = tid & 63;
    int ig = tid >> 6;
    float acc[8];
#pragma unroll
    for (int i = 0; i < 8; i++) acc[i] = 0.f;
#pragma unroll 8
    for (int k = 0; k < 64; k++) {
        float wv = Ws[k * 64 + f];
#pragma unroll
        for (int i = 0; i < 8; i++)
            acc[i] += As[(ig * 8 + i) * 64 + k] * wv;
    }
    float bv = bias[f];
#pragma unroll
    for (int i = 0; i < 8; i++) L[ig * 8 + i][f] = acc[i] + bv;
    __syncthreads();
    int w = tid >> 5, lane = tid & 31;
#pragma unroll
    for (int j = 0; j < 4; j++) {
        int r = w * 4 + j;
        int node = base + r;
        if (node >= N_NODES) break;
        float v0 = L[r][lane], v1 = L[r][lane + 32];
        float m = fmaxf(v0, v1);
        for (int o = 16; o; o >>= 1) m = fmaxf(m, __shfl_xor_sync(0xffffffffu, m, o));
        float s = __expf(v0 - m) + __expf(v1 - m);
        for (int o = 16; o; o >>= 1) s += __shfl_xor_sync(0xffffffffu, s, o);
        float ls = m + __logf(s);
        out[node * 64 + lane]      = v0 - ls;
        out[node * 64 + lane + 32] = v1 - ls;
    }
}

// ---------------- host ----------------
extern "C" void kernel_launch(void* const* d_in, const int* in_sizes, int n_in,
                              void* d_out, int out_size) {
    const float* x   = (const float*)d_in[0];
    const void*  ei  = d_in[1];            // int32 or int64, detected on device
    const float* W1  = (const float*)d_in[2];
    const float* b1  = (const float*)d_in[3];
    const float* W2  = (const float*)d_in[4];
    const float* b2  = (const float*)d_in[5];
    const float* Wx  = (const float*)d_in[6];   // [2,64,64]
    const float* bx  = (const float*)d_in[7];   // [2,64]
    const float* g1  = (const float*)d_in[8];
    const float* be1 = (const float*)d_in[9];
    const float* g2  = (const float*)d_in[10];
    const float* be2 = (const float*)d_in[11];
    const float* g3  = (const float*)d_in[12];
    const float* be3 = (const float*)d_in[13];
    const float* Wfc = (const float*)d_in[14];
    const float* bfc = (const float*)d_in[15];
    float* out = (float*)d_out;

    __half *hA, *hB, *h0;
    cudaGetSymbolAddress((void**)&hA, g_hA);
    cudaGetSymbolAddress((void**)&hB, g_hB);
    cudaGetSymbolAddress((void**)&h0, g_h0);

    // ---- build normalized CSR (by dst, even-padded rows) ----
    init_kernel<<<(N_NODES + 255) / 256, 256>>>((const int*)ei);
    count_deg_kernel<<<(N_EDGES + 255) / 256, 256>>>(ei);
    scan_kernel<<<1, 1024>>>();
    fill_csr_kernel<<<(E2 + 255) / 256, 256>>>(ei);

    const int GEMM_GRID = (N_NODES + 127) / 128;   // 391
    const int FC_GRID   = (N_NODES + 31) / 32;     // 1563
    const int SPMM_GRID = N_NODES / 8;             // 6250

    // ---- layer 1 (IN_F=128 fp32 input, no BN) ----
    gemm_mma_kernel<128, -1, float><<<GEMM_GRID, 256>>>(x, W1, nullptr, hB, nullptr, nullptr);
    spmm_kernel<true><<<SPMM_GRID, 256>>>(hB, hA, b1, nullptr, 1.f, 0.f, 0);
    // ---- layer 2 (BN set 0 fused into GEMM input) ----
    gemm_mma_kernel<64, 0, __half><<<GEMM_GRID, 256>>>(hA, W2, nullptr, hB, g1, be1);
    spmm_kernel<true><<<SPMM_GRID, 256>>>(hB, hA, b2, nullptr, 1.f, 0.f, 1);
    // ---- extra layer 0 (BN set 1) ----
    gemm_mma_kernel<64, 1, __half><<<GEMM_GRID, 256>>>(hA, Wx, nullptr, hB, g2, be2);
    spmm_kernel<true><<<SPMM_GRID, 256>>>(hB, hA, bx, nullptr, 1.f, 0.f, 2);
    // ---- extra layer 1 (BN set 2) ----
    gemm_mma_kernel<64, 2, __half><<<GEMM_GRID, 256>>>(hA, Wx + 64 * 64, nullptr, hB, g3, be3);
    spmm_kernel<true><<<SPMM_GRID, 256>>>(hB, hA, bx + 64, nullptr, 1.f, 0.f, 3);
    // ---- final BN apply (set 3) -> hA normalized, h0 copy ----
    bn_apply_final_kernel<<<(N_NODES * 32) / 256, 256>>>(hA, h0, g3, be3);

    // ---- APPNP: 10 steps, ping-pong hA <-> hB ----
    __half* cur = hA;
    __half* nxt = hB;
    for (int it = 0; it < 10; it++) {
        spmm_kernel<false><<<SPMM_GRID, 256>>>(cur, nxt, nullptr, h0, 0.9f, 0.1f, 0);
        __half* t = cur; cur = nxt; nxt = t;
    }
    // result in hA

    // ---- head: FC + log_softmax fused ----
    fc_logsoftmax_kernel<<<FC_GRID, 256>>>(cur, Wfc, bfc, out);
}

// round 16
// speedup vs baseline: 1.2169x; 1.0326x over previous
#include <cuda_runtime.h>
#include <cuda_fp16.h>
#include <mma.h>

using namespace nvcuda;

#define N_NODES 50000
#define N_EDGES 800000
#define E2      850000   // edges + self loops
#define EPADMAX (E2 + N_NODES)   // worst-case even-padded CSR
#define IN_F    128
#define HID     64
#define BN_EPS  1e-5f
#define INV_Nf  (1.0f / 50000.0f)

// ---------------- scratch (device globals; no allocation allowed) ----------------
__device__ int    g_is64;
__device__ int    g_deg[N_NODES];         // zeroed by memset; self-loop added in scan
__device__ int    g_fill[N_NODES];        // seeded with rowptr by scan
__device__ float  g_dinv[N_NODES];
__device__ int    g_rowptr[N_NODES + 1];
__device__ __align__(16) int2 g_cw[EPADMAX + 4];  // {col, weight-bits}; rows even-padded
__device__ __half g_hA[N_NODES * HID];
__device__ __half g_hB[N_NODES * HID];
__device__ __half g_h0[N_NODES * HID];
__device__ float  g_sumf[4][HID];
__device__ float  g_sqf[4][HID];

// ---------------- count_deg with per-block dtype detection ----------------
// int64 little-endian with values < 50000 -> odd 32-bit words all zero.
__global__ void count_deg_kernel(const void* __restrict__ ei) {
    __shared__ int s64;
    const int* e32 = (const int*)ei;
    if (threadIdx.x < 32) {
        int nz = 0;
        #pragma unroll
        for (int i = 0; i < 4; i++) nz += (e32[2 * (threadIdx.x * 4 + i) + 1] != 0);
        unsigned any = __any_sync(0xffffffffu, nz != 0);
        if (threadIdx.x == 0) s64 = any ? 0 : 1;
    }
    __syncthreads();
    int is64 = s64;
    int e = blockIdx.x * blockDim.x + threadIdx.x;
    if (e == 0) g_is64 = is64;            // published for fill_csr (later launch)
    if (e < N_EDGES) {
        int d = is64 ? (int)((const long long*)ei)[(long long)N_EDGES + e]
                     : e32[N_EDGES + e];
        d = min(max(d, 0), N_NODES - 1);  // crash insurance
        atomicAdd(&g_deg[d], 1);
    }
}

// single-block COALESCED scan over EVEN-PADDED degrees (deg+1 self-loop added here);
// writes dinv, rowptr, seeds g_fill = rowptr, zero-fills each row's pad slot.
__global__ void scan_kernel() {
    __shared__ int wsum[32], woff[32];
    const int REG = (N_NODES + 31) / 32;     // 1563 per warp region
    int wid  = threadIdx.x >> 5;
    int lane = threadIdx.x & 31;
    int base = wid * REG;
    int tot = 0;
    for (int i = 0; i < REG; i += 32) {
        int off = i + lane;
        int idx = base + off;
        int d = 0;
        if (off < REG && idx < N_NODES) {
            int dg = g_deg[idx] + 1;         // + self loop
            g_dinv[idx] = rsqrtf((float)dg);
            d = dg + (dg & 1);               // even-padded length
        }
        tot += d;
    }
    for (int o = 16; o; o >>= 1) tot += __shfl_xor_sync(0xffffffffu, tot, o);
    if (lane == 0) wsum[wid] = tot;
    __syncthreads();
    if (threadIdx.x < 32) {
        int v  = wsum[threadIdx.x];
        int ex = v;
        for (int o = 1; o < 32; o <<= 1) {
            int nb = __shfl_up_sync(0xffffffffu, ex, o);
            if (lane >= o) ex += nb;
        }
        woff[threadIdx.x] = ex - v;
        if (threadIdx.x == 31) g_rowptr[N_NODES] = ex;
    }
    __syncthreads();
    int run = woff[wid];
    for (int i = 0; i < REG; i += 32) {
        int off = i + lane;
        int idx = base + off;
        bool ok = (off < REG) && (idx < N_NODES);
        int dg = ok ? (g_deg[idx] + 1) : 0;
        int d  = dg + (dg & 1);
        int ex = d;
        for (int o = 1; o < 32; o <<= 1) {
            int nb = __shfl_up_sync(0xffffffffu, ex, o);
            if (lane >= o) ex += nb;
        }
        int rowtot = __shfl_sync(0xffffffffu, ex, 31);
        ex -= d;
        if (ok) {
            int rp = run + ex;
            g_rowptr[idx] = rp;
            g_fill[idx]   = rp;
            if (dg & 1) g_cw[rp + dg] = make_int2(0, 0);  // zero-weight pad slot
        }
        run += rowtot;
    }
}

// fill CSR: 2 edges per thread, paired vector index loads
__global__ void fill_csr_kernel(const void* __restrict__ ei) {
    int t = blockIdx.x * blockDim.x + threadIdx.x;
    if (t >= E2 / 2) return;
    int is64 = g_is64;
    int s0, d0, s1, d1;
    if (t < N_EDGES / 2) {
        if (is64) {
            longlong2 sp = ((const longlong2*)ei)[t];
            longlong2 dp = ((const longlong2*)ei)[N_EDGES / 2 + t];
            s0 = (int)sp.x; s1 = (int)sp.y; d0 = (int)dp.x; d1 = (int)dp.y;
        } else {
            int2 sp = ((const int2*)ei)[t];
            int2 dp = ((const int2*)ei)[N_EDGES / 2 + t];
            s0 = sp.x; s1 = sp.y; d0 = dp.x; d1 = dp.y;
        }
        s0 = min(max(s0, 0), N_NODES - 1); d0 = min(max(d0, 0), N_NODES - 1);
        s1 = min(max(s1, 0), N_NODES - 1); d1 = min(max(d1, 0), N_NODES - 1);
    } else {
        int b = (t - N_EDGES / 2) * 2;       // self loops
        s0 = d0 = b; s1 = d1 = b + 1;
    }
    int p0 = atomicAdd(&g_fill[d0], 1);
    g_cw[p0] = make_int2(s0, __float_as_int(g_dinv[s0] * g_dinv[d0]));
    int p1 = atomicAdd(&g_fill[d1], 1);
    g_cw[p1] = make_int2(s1, __float_as_int(g_dinv[s1] * g_dinv[d1]));
}

// ---------------- SpMM (fp16 h): champion form — warp per node, 8-deep MLP ----------------
template <bool STATS>
__global__ __launch_bounds__(256) void spmm_kernel(
    const __half* __restrict__ hin, __half* __restrict__ hout,
    const float* __restrict__ bias, const __half* __restrict__ h0p,
    float wacc, float wh0, int set)
{
    __shared__ float ss[STATS ? 8 : 1][STATS ? HID : 1];
    __shared__ float qq[STATS ? 8 : 1][STATS ? HID : 1];
    int warp = threadIdx.x >> 5;
    int node = blockIdx.x * 8 + warp;
    int lane = threadIdx.x & 31;
    const __half2* __restrict__ hin2 = (const __half2*)hin;
    const int4*    __restrict__ cw4  = (const int4*)g_cw;
    int beg = g_rowptr[node];
    int end = g_rowptr[node + 1];
    float2 a0 = make_float2(0.f, 0.f), a1 = a0, a2 = a0, a3 = a0;
    int e = beg;
    for (; e + 7 < end; e += 8) {
        int4 q0 = cw4[e >> 1];
        int4 q1 = cw4[(e >> 1) + 1];
        int4 q2 = cw4[(e >> 1) + 2];
        int4 q3 = cw4[(e >> 1) + 3];
        float2 v0 = __half22float2(hin2[q0.x*32 + lane]);
        float2 v1 = __half22float2(hin2[q0.z*32 + lane]);
        float2 v2 = __half22float2(hin2[q1.x*32 + lane]);
        float2 v3 = __half22float2(hin2[q1.z*32 + lane]);
        float2 v4 = __half22float2(hin2[q2.x*32 + lane]);
        float2 v5 = __half22float2(hin2[q2.z*32 + lane]);
        float2 v6 = __half22float2(hin2[q3.x*32 + lane]);
        float2 v7 = __half22float2(hin2[q3.z*32 + lane]);
        float w0 = __int_as_float(q0.y), w1 = __int_as_float(q0.w);
        float w2 = __int_as_float(q1.y), w3 = __int_as_float(q1.w);
        float w4 = __int_as_float(q2.y), w5 = __int_as_float(q2.w);
        float w6 = __int_as_float(q3.y), w7 = __int_as_float(q3.w);
        a0.x += w0*v0.x; a0.y += w0*v0.y;
        a1.x += w1*v1.x; a1.y += w1*v1.y;
        a2.x += w2*v2.x; a2.y += w2*v2.y;
        a3.x += w3*v3.x; a3.y += w3*v3.y;
        a0.x += w4*v4.x; a0.y += w4*v4.y;
        a1.x += w5*v5.x; a1.y += w5*v5.y;
        a2.x += w6*v6.x; a2.y += w6*v6.y;
        a3.x += w7*v7.x; a3.y += w7*v7.y;
    }
    for (; e < end; e += 2) {                 // even tail (rows are even-padded)
        int4 q0 = cw4[e >> 1];
        float2 v0 = __half22float2(hin2[q0.x*32 + lane]);
        float2 v1 = __half22float2(hin2[q0.z*32 + lane]);
        float w0 = __int_as_float(q0.y), w1 = __int_as_float(q0.w);
        a0.x += w0*v0.x; a0.y += w0*v0.y;
        a1.x += w1*v1.x; a1.y += w1*v1.y;
    }
    float2 r;
    r.x = ((a0.x + a1.x) + (a2.x + a3.x)) * wacc;
    r.y = ((a0.y + a1.y) + (a2.y + a3.y)) * wacc;
    if (bias) {
        float2 b = ((const float2*)bias)[lane];
        r.x += b.x; r.y += b.y;
    }
    if (h0p) {
        float2 z = __half22float2(((const __half2*)h0p)[node*32 + lane]);
        r.x += wh0 * z.x; r.y += wh0 * z.y;
    }
    ((__half2*)hout)[node*32 + lane] = __floats2half2_rn(r.x, r.y);
    if (STATS) {
        ss[warp][2*lane]     = r.x;
        ss[warp][2*lane + 1] = r.y;
        qq[warp][2*lane]     = r.x * r.x;
        qq[warp][2*lane + 1] = r.y * r.y;
        __syncthreads();
        int t = threadIdx.x;
        if (t < HID) {
            float s = 0.f;
#pragma unroll
            for (int g = 0; g < 8; g++) s += ss[g][t];
            atomicAdd(&g_sumf[set][t], s);
        } else if (t < 2 * HID) {
            float q = 0.f;
#pragma unroll
            for (int g = 0; g < 8; g++) q += qq[g][t - HID];
            atomicAdd(&g_sqf[set][t - HID], q);
        }
    }
}

// ---------------- tensor-core GEMM: block = 128 nodes x 64 features, wmma 16x16x16 ----------------
template <int KIN, int BNSET, typename TA>
__global__ __launch_bounds__(256) void gemm_mma_kernel(
    const TA* __restrict__ A, const float* __restrict__ W,
    const float* __restrict__ bias, __half* __restrict__ C,
    const float* __restrict__ gam, const float* __restrict__ bet)
{
    struct Stage { __half As[128][72]; __half Ws[64][72]; };
    __shared__ union U { Stage st; float Cs[128][68]; U(){} } SM;
    __shared__ float sc[HID], sh[HID];
    int tid  = threadIdx.x;
    int warp = tid >> 5;
    if (BNSET >= 0) {
        if (tid < HID) {
            float mean = g_sumf[BNSET][tid] * INV_Nf;
            float var  = g_sqf[BNSET][tid] * INV_Nf - mean * mean;
            float s = gam[tid] * rsqrtf(var + BN_EPS);
            sc[tid] = s;
            sh[tid] = bet[tid] - mean * s;
        }
        __syncthreads();
    }
    int base = blockIdx.x * 128;
    wmma::fragment<wmma::accumulator, 16, 16, 16, float> acc[4];
#pragma unroll
    for (int i = 0; i < 4; i++) wmma::fill_fragment(acc[i], 0.f);

    for (int k0 = 0; k0 < KIN; k0 += 64) {
        __syncthreads();
        for (int i = tid; i < 128 * 32; i += 256) {
            int r = i >> 5, c = (i & 31) * 2;
            float v0 = 0.f, v1 = 0.f;
            if (base + r < N_NODES) {
                if constexpr (sizeof(TA) == 2) {
                    float2 p = __half22float2(((const __half2*)A)[((base + r) * KIN + k0 + c) >> 1]);
                    v0 = p.x; v1 = p.y;
                } else {
                    float2 p = ((const float2*)A)[((base + r) * KIN + k0 + c) >> 1];
                    v0 = p.x; v1 = p.y;
                }
            }
            if (BNSET >= 0) {
                v0 = fmaxf(fmaf(v0, sc[k0 + c],     sh[k0 + c]),     0.f);
                v1 = fmaxf(fmaf(v1, sc[k0 + c + 1], sh[k0 + c + 1]), 0.f);
            }
            *reinterpret_cast<__half2*>(&SM.st.As[r][c]) = __floats2half2_rn(v0, v1);
        }
        for (int i = tid; i < 64 * 32; i += 256) {
            int k = i >> 5, n = (i & 31) * 2;
            float2 p = ((const float2*)W)[((k0 + k) * 64 + n) >> 1];
            *reinterpret_cast<__half2*>(&SM.st.Ws[k][n]) = __floats2half2_rn(p.x, p.y);
        }
        __syncthreads();
        int r0 = warp * 16;
#pragma unroll
        for (int kk = 0; kk < 64; kk += 16) {
            wmma::fragment<wmma::matrix_a, 16, 16, 16, __half, wmma::row_major> af;
            wmma::load_matrix_sync(af, &SM.st.As[r0][kk], 72);
#pragma unroll
            for (int nt = 0; nt < 4; nt++) {
                wmma::fragment<wmma::matrix_b, 16, 16, 16, __half, wmma::row_major> bf;
                wmma::load_matrix_sync(bf, &SM.st.Ws[kk][nt * 16], 72);
                wmma::mma_sync(acc[nt], af, bf, acc[nt]);
            }
        }
    }
    __syncthreads();   // As/Ws dead; Cs aliases them
#pragma unroll
    for (int nt = 0; nt < 4; nt++)
        wmma::store_matrix_sync(&SM.Cs[warp * 16][nt * 16], acc[nt], 68, wmma::mem_row_major);
    __syncthreads();
    for (int i = tid; i < 128 * 32; i += 256) {
        int r = i >> 5, c = (i & 31) * 2;
        int node = base + r;
        if (node < N_NODES) {
            float b0 = bias ? bias[c]     : 0.f;
            float b1 = bias ? bias[c + 1] : 0.f;
            ((__half2*)C)[(node * 64 + c) >> 1] =
                __floats2half2_rn(SM.Cs[r][c] + b0, SM.Cs[r][c + 1] + b1);
        }
    }
}

// ---------------- layer-4 BN apply (inline finalize) -> writes h and h0 (fp16) ----------------
__global__ __launch_bounds__(256) void bn_apply_final_kernel(
    __half* __restrict__ h, __half* __restrict__ h0,
    const float* __restrict__ gam, const float* __restrict__ bet)
{
    __shared__ float sc[HID], sh[HID];
    int tid = threadIdx.x;
    if (tid < HID) {
        float mean = g_sumf[3][tid] * INV_Nf;
        float var  = g_sqf[3][tid] * INV_Nf - mean * mean;
        float s = gam[tid] * rsqrtf(var + BN_EPS);
        sc[tid] = s;
        sh[tid] = bet[tid] - mean * s;
    }
    __syncthreads();
    int i = blockIdx.x * blockDim.x + tid;   // over N*32 half2s (exact)
    float2 v = __half22float2(((const __half2*)h)[i]);
    int f = (i * 2) & (HID - 1);
    v.x = fmaxf(fmaf(v.x, sc[f],     sh[f]),     0.f);
    v.y = fmaxf(fmaf(v.y, sc[f + 1], sh[f + 1]), 0.f);
    __half2 o = __floats2half2_rn(v.x, v.y);
    ((__half2*)h)[i]  = o;
    ((__half2*)h0)[i] = o;
}

// ---------------- fc head: wmma GEMM + fused log-softmax, 128 rows/block ----------------
__global__ __launch_bounds__(256) void fc_mma_logsoftmax_kernel(
    const __half* __restrict__ A, const float* __restrict__ W,
    const float* __restrict__ bias, float* __restrict__ out)
{
    struct Stage { __half As[128][72]; __half Ws[64][72]; };
    __shared__ union U { Stage st; float Cs[128][68]; U(){} } SM;
    int tid  = threadIdx.x;
    int warp = tid >> 5;
    int lane = tid & 31;
    int base = blockIdx.x * 128;
    for (int i = tid; i < 128 * 32; i += 256) {
        int r = i >> 5, c = (i & 31) * 2;
        __half2 p = __floats2half2_rn(0.f, 0.f);
        if (base + r < N_NODES)
            p = ((const __half2*)A)[((base + r) * 64 + c) >> 1];
        *reinterpret_cast<__half2*>(&SM.st.As[r][c]) = p;
    }
    for (int i = tid; i < 64 * 32; i += 256) {
        int k = i >> 5, n = (i & 31) * 2;
        float2 p = ((const float2*)W)[(k * 64 + n) >> 1];
        *reinterpret_cast<__half2*>(&SM.st.Ws[k][n]) = __floats2half2_rn(p.x, p.y);
    }
    __syncthreads();
    wmma::fragment<wmma::accumulator, 16, 16, 16, float> acc[4];
#pragma unroll
    for (int i = 0; i < 4; i++) wmma::fill_fragment(acc[i], 0.f);
    int r0 = warp * 16;
#pragma unroll
    for (int kk = 0; kk < 64; kk += 16) {
        wmma::fragment<wmma::matrix_a, 16, 16, 16, __half, wmma::row_major> af;
        wmma::load_matrix_sync(af, &SM.st.As[r0][kk], 72);
#pragma unroll
        for (int nt = 0; nt < 4; nt++) {
            wmma::fragment<wmma::matrix_b, 16, 16, 16, __half, wmma::row_major> bf;
            wmma::load_matrix_sync(bf, &SM.st.Ws[kk][nt * 16], 72);
            wmma::mma_sync(acc[nt], af, bf, acc[nt]);
        }
    }
    __syncthreads();
#pragma unroll
    for (int nt = 0; nt < 4; nt++)
        wmma::store_matrix_sync(&SM.Cs[warp * 16][nt * 16], acc[nt], 68, wmma::mem_row_major);
    __syncthreads();
    // log-softmax: each warp handles its 16 rows; lanes cover 64 classes (2 each)
    float bl0 = bias[lane], bl1 = bias[lane + 32];
#pragma unroll
    for (int j = 0; j < 16; j++) {
        int r = warp * 16 + j;
        int node = base + r;
        if (node >= N_NODES) break;
        float v0 = SM.Cs[r][lane]      + bl0;
        float v1 = SM.Cs[r][lane + 32] + bl1;
        float m = fmaxf(v0, v1);
        for (int o = 16; o; o >>= 1) m = fmaxf(m, __shfl_xor_sync(0xffffffffu, m, o));
        float s = __expf(v0 - m) + __expf(v1 - m);
        for (int o = 16; o; o >>= 1) s += __shfl_xor_sync(0xffffffffu, s, o);
        float ls = m + __logf(s);
        out[node * 64 + lane]      = v0 - ls;
        out[node * 64 + lane + 32] = v1 - ls;
    }
}

// ---------------- host ----------------
extern "C" void kernel_launch(void* const* d_in, const int* in_sizes, int n_in,
                              void* d_out, int out_size) {
    const float* x   = (const float*)d_in[0];
    const void*  ei  = d_in[1];            // int32 or int64, detected on device
    const float* W1  = (const float*)d_in[2];
    const float* b1  = (const float*)d_in[3];
    const float* W2  = (const float*)d_in[4];
    const float* b2  = (const float*)d_in[5];
    const float* Wx  = (const float*)d_in[6];   // [2,64,64]
    const float* bx  = (const float*)d_in[7];   // [2,64]
    const float* g1  = (const float*)d_in[8];
    const float* be1 = (const float*)d_in[9];
    const float* g2  = (const float*)d_in[10];
    const float* be2 = (const float*)d_in[11];
    const float* g3  = (const float*)d_in[12];
    const float* be3 = (const float*)d_in[13];
    const float* Wfc = (const float*)d_in[14];
    const float* bfc = (const float*)d_in[15];
    float* out = (float*)d_out;

    __half *hA, *hB, *h0;
    cudaGetSymbolAddress((void**)&hA, g_hA);
    cudaGetSymbolAddress((void**)&hB, g_hB);
    cudaGetSymbolAddress((void**)&h0, g_h0);
    void *degp, *sump, *sqp;
    cudaGetSymbolAddress(&degp, g_deg);
    cudaGetSymbolAddress(&sump, g_sumf);
    cudaGetSymbolAddress(&sqp,  g_sqf);

    // ---- build normalized CSR (by dst, even-padded rows) ----
    cudaMemsetAsync(degp, 0, N_NODES * sizeof(int));
    cudaMemsetAsync(sump, 0, 4 * HID * sizeof(float));
    cudaMemsetAsync(sqp,  0, 4 * HID * sizeof(float));
    count_deg_kernel<<<(N_EDGES + 255) / 256, 256>>>(ei);
    scan_kernel<<<1, 1024>>>();
    fill_csr_kernel<<<(E2 / 2 + 255) / 256, 256>>>(ei);

    const int GEMM_GRID = (N_NODES + 127) / 128;   // 391
    const int SPMM_GRID = N_NODES / 8;             // 6250

    // ---- layer 1 (IN_F=128 fp32 input, no BN) ----
    gemm_mma_kernel<128, -1, float><<<GEMM_GRID, 256>>>(x, W1, nullptr, hB, nullptr, nullptr);
    spmm_kernel<true><<<SPMM_GRID, 256>>>(hB, hA, b1, nullptr, 1.f, 0.f, 0);
    // ---- layer 2 (BN set 0 fused into GEMM input) ----
    gemm_mma_kernel<64, 0, __half><<<GEMM_GRID, 256>>>(hA, W2, nullptr, hB, g1, be1);
    spmm_kernel<true><<<SPMM_GRID, 256>>>(hB, hA, b2, nullptr, 1.f, 0.f, 1);
    // ---- extra layer 0 (BN set 1) ----
    gemm_mma_kernel<64, 1, __half><<<GEMM_GRID, 256>>>(hA, Wx, nullptr, hB, g2, be2);
    spmm_kernel<true><<<SPMM_GRID, 256>>>(hB, hA, bx, nullptr, 1.f, 0.f, 2);
    // ---- extra layer 1 (BN set 2) ----
    gemm_mma_kernel<64, 2, __half><<<GEMM_GRID, 256>>>(hA, Wx + 64 * 64, nullptr, hB, g3, be3);
    spmm_kernel<true><<<SPMM_GRID, 256>>>(hB, hA, bx + 64, nullptr, 1.f, 0.f, 3);
    // ---- final BN apply (set 3) -> hA normalized, h0 copy ----
    bn_apply_final_kernel<<<(N_NODES * 32) / 256, 256>>>(hA, h0, g3, be3);

    // ---- APPNP: 10 steps, ping-pong hA <-> hB ----
    __half* cur = hA;
    __half* nxt = hB;
    for (int it = 0; it < 10; it++) {
        spmm_kernel<false><<<SPMM_GRID, 256>>>(cur, nxt, nullptr, h0, 0.9f, 0.1f, 0);
        __half* t = cur; cur = nxt; nxt = t;
    }
    // result in hA

    // ---- head: wmma FC + fused log_softmax ----
    fc_mma_logsoftmax_kernel<<<GEMM_GRID, 256>>>(cur, Wfc, bfc, out);
}

// round 17
// speedup vs baseline: 1.2227x; 1.0048x over previous
#include <cuda_runtime.h>
#include <cuda_fp16.h>
#include <mma.h>

using namespace nvcuda;

#define N_NODES 50000
#define N_EDGES 800000
#define E2      850000   // edges + self loops
#define EPADMAX (E2 + N_NODES)   // worst-case even-padded CSR
#define IN_F    128
#define HID     64
#define BN_EPS  1e-5f
#define INV_Nf  (1.0f / 50000.0f)

// ---------------- scratch (device globals; no allocation allowed) ----------------
__device__ int    g_is64;
__device__ int    g_deg[N_NODES];         // zeroed by memset; self-loop added in scan
__device__ int    g_fill[N_NODES];        // seeded with rowptr by scan
__device__ float  g_dinv[N_NODES];
__device__ int    g_rowptr[N_NODES + 1];
__device__ __align__(16) int2 g_cw[EPADMAX + 4];  // {col, weight-bits}; rows even-padded
__device__ __half g_hA[N_NODES * HID];
__device__ __half g_hB[N_NODES * HID];
__device__ __half g_h0[N_NODES * HID];
__device__ float  g_sumf[4][HID];
__device__ float  g_sqf[4][HID];

// ---------------- count_deg with per-block dtype detection ----------------
// int64 little-endian with values < 50000 -> odd 32-bit words all zero.
__global__ void count_deg_kernel(const void* __restrict__ ei) {
    __shared__ int s64;
    const int* e32 = (const int*)ei;
    if (threadIdx.x < 32) {
        int nz = 0;
        #pragma unroll
        for (int i = 0; i < 4; i++) nz += (e32[2 * (threadIdx.x * 4 + i) + 1] != 0);
        unsigned any = __any_sync(0xffffffffu, nz != 0);
        if (threadIdx.x == 0) s64 = any ? 0 : 1;
    }
    __syncthreads();
    int is64 = s64;
    int e = blockIdx.x * blockDim.x + threadIdx.x;
    if (e == 0) g_is64 = is64;            // published for fill_csr (later launch)
    if (e < N_EDGES) {
        int d = is64 ? (int)((const long long*)ei)[(long long)N_EDGES + e]
                     : e32[N_EDGES + e];
        d = min(max(d, 0), N_NODES - 1);  // crash insurance
        atomicAdd(&g_deg[d], 1);
    }
}

// single-block COALESCED scan over EVEN-PADDED degrees (deg+1 self-loop added here);
// writes dinv, rowptr, seeds g_fill = rowptr, zero-fills each row's pad slot.
__global__ void scan_kernel() {
    __shared__ int wsum[32], woff[32];
    const int REG = (N_NODES + 31) / 32;     // 1563 per warp region
    int wid  = threadIdx.x >> 5;
    int lane = threadIdx.x & 31;
    int base = wid * REG;
    int tot = 0;
    for (int i = 0; i < REG; i += 32) {
        int off = i + lane;
        int idx = base + off;
        int d = 0;
        if (off < REG && idx < N_NODES) {
            int dg = g_deg[idx] + 1;         // + self loop
            g_dinv[idx] = rsqrtf((float)dg);
            d = dg + (dg & 1);               // even-padded length
        }
        tot += d;
    }
    for (int o = 16; o; o >>= 1) tot += __shfl_xor_sync(0xffffffffu, tot, o);
    if (lane == 0) wsum[wid] = tot;
    __syncthreads();
    if (threadIdx.x < 32) {
        int v  = wsum[threadIdx.x];
        int ex = v;
        for (int o = 1; o < 32; o <<= 1) {
            int nb = __shfl_up_sync(0xffffffffu, ex, o);
            if (lane >= o) ex += nb;
        }
        woff[threadIdx.x] = ex - v;
        if (threadIdx.x == 31) g_rowptr[N_NODES] = ex;
    }
    __syncthreads();
    int run = woff[wid];
    for (int i = 0; i < REG; i += 32) {
        int off = i + lane;
        int idx = base + off;
        bool ok = (off < REG) && (idx < N_NODES);
        int dg = ok ? (g_deg[idx] + 1) : 0;
        int d  = dg + (dg & 1);
        int ex = d;
        for (int o = 1; o < 32; o <<= 1) {
            int nb = __shfl_up_sync(0xffffffffu, ex, o);
            if (lane >= o) ex += nb;
        }
        int rowtot = __shfl_sync(0xffffffffu, ex, 31);
        ex -= d;
        if (ok) {
            int rp = run + ex;
            g_rowptr[idx] = rp;
            g_fill[idx]   = rp;
            if (dg & 1) g_cw[rp + dg] = make_int2(0, 0);  // zero-weight pad slot
        }
        run += rowtot;
    }
}

// fill CSR: 2 edges per thread, paired vector index loads
__global__ void fill_csr_kernel(const void* __restrict__ ei) {
    int t = blockIdx.x * blockDim.x + threadIdx.x;
    if (t >= E2 / 2) return;
    int is64 = g_is64;
    int s0, d0, s1, d1;
    if (t < N_EDGES / 2) {
        if (is64) {
            longlong2 sp = ((const longlong2*)ei)[t];
            longlong2 dp = ((const longlong2*)ei)[N_EDGES / 2 + t];
            s0 = (int)sp.x; s1 = (int)sp.y; d0 = (int)dp.x; d1 = (int)dp.y;
        } else {
            int2 sp = ((const int2*)ei)[t];
            int2 dp = ((const int2*)ei)[N_EDGES / 2 + t];
            s0 = sp.x; s1 = sp.y; d0 = dp.x; d1 = dp.y;
        }
        s0 = min(max(s0, 0), N_NODES - 1); d0 = min(max(d0, 0), N_NODES - 1);
        s1 = min(max(s1, 0), N_NODES - 1); d1 = min(max(d1, 0), N_NODES - 1);
    } else {
        int b = (t - N_EDGES / 2) * 2;       // self loops
        s0 = d0 = b; s1 = d1 = b + 1;
    }
    int p0 = atomicAdd(&g_fill[d0], 1);
    g_cw[p0] = make_int2(s0, __float_as_int(g_dinv[s0] * g_dinv[d0]));
    int p1 = atomicAdd(&g_fill[d1], 1);
    g_cw[p1] = make_int2(s1, __float_as_int(g_dinv[s1] * g_dinv[d1]));
}

// ---------------- SpMM (fp16 h): champion form — warp per node, 8-deep MLP ----------------
template <bool STATS>
__global__ __launch_bounds__(256) void spmm_kernel(
    const __half* __restrict__ hin, __half* __restrict__ hout,
    const float* __restrict__ bias, const __half* __restrict__ h0p,
    float wacc, float wh0, int set)
{
    __shared__ float ss[STATS ? 8 : 1][STATS ? HID : 1];
    __shared__ float qq[STATS ? 8 : 1][STATS ? HID : 1];
    int warp = threadIdx.x >> 5;
    int node = blockIdx.x * 8 + warp;
    int lane = threadIdx.x & 31;
    const __half2* __restrict__ hin2 = (const __half2*)hin;
    const int4*    __restrict__ cw4  = (const int4*)g_cw;
    int beg = g_rowptr[node];
    int end = g_rowptr[node + 1];
    float2 a0 = make_float2(0.f, 0.f), a1 = a0, a2 = a0, a3 = a0;
    int e = beg;
    for (; e + 7 < end; e += 8) {
        int4 q0 = cw4[e >> 1];
        int4 q1 = cw4[(e >> 1) + 1];
        int4 q2 = cw4[(e >> 1) + 2];
        int4 q3 = cw4[(e >> 1) + 3];
        float2 v0 = __half22float2(hin2[q0.x*32 + lane]);
        float2 v1 = __half22float2(hin2[q0.z*32 + lane]);
        float2 v2 = __half22float2(hin2[q1.x*32 + lane]);
        float2 v3 = __half22float2(hin2[q1.z*32 + lane]);
        float2 v4 = __half22float2(hin2[q2.x*32 + lane]);
        float2 v5 = __half22float2(hin2[q2.z*32 + lane]);
        float2 v6 = __half22float2(hin2[q3.x*32 + lane]);
        float2 v7 = __half22float2(hin2[q3.z*32 + lane]);
        float w0 = __int_as_float(q0.y), w1 = __int_as_float(q0.w);
        float w2 = __int_as_float(q1.y), w3 = __int_as_float(q1.w);
        float w4 = __int_as_float(q2.y), w5 = __int_as_float(q2.w);
        float w6 = __int_as_float(q3.y), w7 = __int_as_float(q3.w);
        a0.x += w0*v0.x; a0.y += w0*v0.y;
        a1.x += w1*v1.x; a1.y += w1*v1.y;
        a2.x += w2*v2.x; a2.y += w2*v2.y;
        a3.x += w3*v3.x; a3.y += w3*v3.y;
        a0.x += w4*v4.x; a0.y += w4*v4.y;
        a1.x += w5*v5.x; a1.y += w5*v5.y;
        a2.x += w6*v6.x; a2.y += w6*v6.y;
        a3.x += w7*v7.x; a3.y += w7*v7.y;
    }
    for (; e < end; e += 2) {                 // even tail (rows are even-padded)
        int4 q0 = cw4[e >> 1];
        float2 v0 = __half22float2(hin2[q0.x*32 + lane]);
        float2 v1 = __half22float2(hin2[q0.z*32 + lane]);
        float w0 = __int_as_float(q0.y), w1 = __int_as_float(q0.w);
        a0.x += w0*v0.x; a0.y += w0*v0.y;
        a1.x += w1*v1.x; a1.y += w1*v1.y;
    }
    float2 r;
    r.x = ((a0.x + a1.x) + (a2.x + a3.x)) * wacc;
    r.y = ((a0.y + a1.y) + (a2.y + a3.y)) * wacc;
    if (bias) {
        float2 b = ((const float2*)bias)[lane];
        r.x += b.x; r.y += b.y;
    }
    if (h0p) {
        float2 z = __half22float2(((const __half2*)h0p)[node*32 + lane]);
        r.x += wh0 * z.x; r.y += wh0 * z.y;
    }
    ((__half2*)hout)[node*32 + lane] = __floats2half2_rn(r.x, r.y);
    if (STATS) {
        ss[warp][2*lane]     = r.x;
        ss[warp][2*lane + 1] = r.y;
        qq[warp][2*lane]     = r.x * r.x;
        qq[warp][2*lane + 1] = r.y * r.y;
        __syncthreads();
        int t = threadIdx.x;
        if (t < HID) {
            float s = 0.f;
#pragma unroll
            for (int g = 0; g < 8; g++) s += ss[g][t];
            atomicAdd(&g_sumf[set][t], s);
        } else if (t < 2 * HID) {
            float q = 0.f;
#pragma unroll
            for (int g = 0; g < 8; g++) q += qq[g][t - HID];
            atomicAdd(&g_sqf[set][t - HID], q);
        }
    }
}

// ---------------- tensor-core GEMM: SINGLE-PASS staging (full K in smem) ----------------
// block = 128 nodes x 64 features; one load phase -> one sync -> all wmma k-steps.
template <int KIN, int BNSET, typename TA>
__global__ __launch_bounds__(256) void gemm_mma_kernel(
    const TA* __restrict__ A, const float* __restrict__ W,
    const float* __restrict__ bias, __half* __restrict__ C,
    const float* __restrict__ gam, const float* __restrict__ bet)
{
    struct Stage { __half As[128][KIN + 8]; __half Ws[KIN][72]; };
    __shared__ union U { Stage st; float Cs[128][68]; U(){} } SM;
    __shared__ float sc[HID], sh[HID];
    int tid  = threadIdx.x;
    int warp = tid >> 5;
    if (BNSET >= 0) {
        if (tid < HID) {
            float mean = g_sumf[BNSET][tid] * INV_Nf;
            float var  = g_sqf[BNSET][tid] * INV_Nf - mean * mean;
            float s = gam[tid] * rsqrtf(var + BN_EPS);
            sc[tid] = s;
            sh[tid] = bet[tid] - mean * s;
        }
        __syncthreads();
    }
    int base = blockIdx.x * 128;
    const int HK = KIN / 2;                   // half2 per row
    // stage FULL A-tile: 128 x KIN, BN+ReLU fused; ~32-64 independent loads/thread
    for (int i = tid; i < 128 * HK; i += 256) {
        int r = i / HK, c = (i - r * HK) * 2;
        float v0 = 0.f, v1 = 0.f;
        if (base + r < N_NODES) {
            if constexpr (sizeof(TA) == 2) {
                float2 p = __half22float2(((const __half2*)A)[((base + r) * KIN + c) >> 1]);
                v0 = p.x; v1 = p.y;
            } else {
                float2 p = ((const float2*)A)[((base + r) * KIN + c) >> 1];
                v0 = p.x; v1 = p.y;
            }
        }
        if (BNSET >= 0) {
            v0 = fmaxf(fmaf(v0, sc[c],     sh[c]),     0.f);
            v1 = fmaxf(fmaf(v1, sc[c + 1], sh[c + 1]), 0.f);
        }
        *reinterpret_cast<__half2*>(&SM.st.As[r][c]) = __floats2half2_rn(v0, v1);
    }
    // stage FULL W: KIN x 64
    for (int i = tid; i < KIN * 32; i += 256) {
        int k = i >> 5, n = (i & 31) * 2;
        float2 p = ((const float2*)W)[(k * 64 + n) >> 1];
        *reinterpret_cast<__half2*>(&SM.st.Ws[k][n]) = __floats2half2_rn(p.x, p.y);
    }
    __syncthreads();
    wmma::fragment<wmma::accumulator, 16, 16, 16, float> acc[4];
#pragma unroll
    for (int i = 0; i < 4; i++) wmma::fill_fragment(acc[i], 0.f);
    int r0 = warp * 16;
#pragma unroll
    for (int kk = 0; kk < KIN; kk += 16) {
        wmma::fragment<wmma::matrix_a, 16, 16, 16, __half, wmma::row_major> af;
        wmma::load_matrix_sync(af, &SM.st.As[r0][kk], KIN + 8);
#pragma unroll
        for (int nt = 0; nt < 4; nt++) {
            wmma::fragment<wmma::matrix_b, 16, 16, 16, __half, wmma::row_major> bf;
            wmma::load_matrix_sync(bf, &SM.st.Ws[kk][nt * 16], 72);
            wmma::mma_sync(acc[nt], af, bf, acc[nt]);
        }
    }
    __syncthreads();   // As/Ws dead; Cs aliases them
#pragma unroll
    for (int nt = 0; nt < 4; nt++)
        wmma::store_matrix_sync(&SM.Cs[warp * 16][nt * 16], acc[nt], 68, wmma::mem_row_major);
    __syncthreads();
    for (int i = tid; i < 128 * 32; i += 256) {
        int r = i >> 5, c = (i & 31) * 2;
        int node = base + r;
        if (node < N_NODES) {
            float b0 = bias ? bias[c]     : 0.f;
            float b1 = bias ? bias[c + 1] : 0.f;
            ((__half2*)C)[(node * 64 + c) >> 1] =
                __floats2half2_rn(SM.Cs[r][c] + b0, SM.Cs[r][c + 1] + b1);
        }
    }
}

// ---------------- layer-4 BN apply (inline finalize) -> writes h and h0 (fp16) ----------------
__global__ __launch_bounds__(256) void bn_apply_final_kernel(
    __half* __restrict__ h, __half* __restrict__ h0,
    const float* __restrict__ gam, const float* __restrict__ bet)
{
    __shared__ float sc[HID], sh[HID];
    int tid = threadIdx.x;
    if (tid < HID) {
        float mean = g_sumf[3][tid] * INV_Nf;
        float var  = g_sqf[3][tid] * INV_Nf - mean * mean;
        float s = gam[tid] * rsqrtf(var + BN_EPS);
        sc[tid] = s;
        sh[tid] = bet[tid] - mean * s;
    }
    __syncthreads();
    int i = blockIdx.x * blockDim.x + tid;   // over N*32 half2s (exact)
    float2 v = __half22float2(((const __half2*)h)[i]);
    int f = (i * 2) & (HID - 1);
    v.x = fmaxf(fmaf(v.x, sc[f],     sh[f]),     0.f);
    v.y = fmaxf(fmaf(v.y, sc[f + 1], sh[f + 1]), 0.f);
    __half2 o = __floats2half2_rn(v.x, v.y);
    ((__half2*)h)[i]  = o;
    ((__half2*)h0)[i] = o;
}

// ---------------- fc head: wmma GEMM + fused log-softmax, 128 rows/block ----------------
__global__ __launch_bounds__(256) void fc_mma_logsoftmax_kernel(
    const __half* __restrict__ A, const float* __restrict__ W,
    const float* __restrict__ bias, float* __restrict__ out)
{
    struct Stage { __half As[128][72]; __half Ws[64][72]; };
    __shared__ union U { Stage st; float Cs[128][68]; U(){} } SM;
    int tid  = threadIdx.x;
    int warp = tid >> 5;
    int lane = tid & 31;
    int base = blockIdx.x * 128;
    for (int i = tid; i < 128 * 32; i += 256) {
        int r = i >> 5, c = (i & 31) * 2;
        __half2 p = __floats2half2_rn(0.f, 0.f);
        if (base + r < N_NODES)
            p = ((const __half2*)A)[((base + r) * 64 + c) >> 1];
        *reinterpret_cast<__half2*>(&SM.st.As[r][c]) = p;
    }
    for (int i = tid; i < 64 * 32; i += 256) {
        int k = i >> 5, n = (i & 31) * 2;
        float2 p = ((const float2*)W)[(k * 64 + n) >> 1];
        *reinterpret_cast<__half2*>(&SM.st.Ws[k][n]) = __floats2half2_rn(p.x, p.y);
    }
    __syncthreads();
    wmma::fragment<wmma::accumulator, 16, 16, 16, float> acc[4];
#pragma unroll
    for (int i = 0; i < 4; i++) wmma::fill_fragment(acc[i], 0.f);
    int r0 = warp * 16;
#pragma unroll
    for (int kk = 0; kk < 64; kk += 16) {
        wmma::fragment<wmma::matrix_a, 16, 16, 16, __half, wmma::row_major> af;
        wmma::load_matrix_sync(af, &SM.st.As[r0][kk], 72);
#pragma unroll
        for (int nt = 0; nt < 4; nt++) {
            wmma::fragment<wmma::matrix_b, 16, 16, 16, __half, wmma::row_major> bf;
            wmma::load_matrix_sync(bf, &SM.st.Ws[kk][nt * 16], 72);
            wmma::mma_sync(acc[nt], af, bf, acc[nt]);
        }
    }
    __syncthreads();
#pragma unroll
    for (int nt = 0; nt < 4; nt++)
        wmma::store_matrix_sync(&SM.Cs[warp * 16][nt * 16], acc[nt], 68, wmma::mem_row_major);
    __syncthreads();
    // log-softmax: each warp handles its 16 rows; lanes cover 64 classes (2 each)
    float bl0 = bias[lane], bl1 = bias[lane + 32];
#pragma unroll
    for (int j = 0; j < 16; j++) {
        int r = warp * 16 + j;
        int node = base + r;
        if (node >= N_NODES) break;
        float v0 = SM.Cs[r][lane]      + bl0;
        float v1 = SM.Cs[r][lane + 32] + bl1;
        float m = fmaxf(v0, v1);
        for (int o = 16; o; o >>= 1) m = fmaxf(m, __shfl_xor_sync(0xffffffffu, m, o));
        float s = __expf(v0 - m) + __expf(v1 - m);
        for (int o = 16; o; o >>= 1) s += __shfl_xor_sync(0xffffffffu, s, o);
        float ls = m + __logf(s);
        out[node * 64 + lane]      = v0 - ls;
        out[node * 64 + lane + 32] = v1 - ls;
    }
}

// ---------------- host ----------------
extern "C" void kernel_launch(void* const* d_in, const int* in_sizes, int n_in,
                              void* d_out, int out_size) {
    const float* x   = (const float*)d_in[0];
    const void*  ei  = d_in[1];            // int32 or int64, detected on device
    const float* W1  = (const float*)d_in[2];
    const float* b1  = (const float*)d_in[3];
    const float* W2  = (const float*)d_in[4];
    const float* b2  = (const float*)d_in[5];
    const float* Wx  = (const float*)d_in[6];   // [2,64,64]
    const float* bx  = (const float*)d_in[7];   // [2,64]
    const float* g1  = (const float*)d_in[8];
    const float* be1 = (const float*)d_in[9];
    const float* g2  = (const float*)d_in[10];
    const float* be2 = (const float*)d_in[11];
    const float* g3  = (const float*)d_in[12];
    const float* be3 = (const float*)d_in[13];
    const float* Wfc = (const float*)d_in[14];
    const float* bfc = (const float*)d_in[15];
    float* out = (float*)d_out;

    __half *hA, *hB, *h0;
    cudaGetSymbolAddress((void**)&hA, g_hA);
    cudaGetSymbolAddress((void**)&hB, g_hB);
    cudaGetSymbolAddress((void**)&h0, g_h0);
    void *degp, *sump, *sqp;
    cudaGetSymbolAddress(&degp, g_deg);
    cudaGetSymbolAddress(&sump, g_sumf);
    cudaGetSymbolAddress(&sqp,  g_sqf);

    // ---- build normalized CSR (by dst, even-padded rows) ----
    cudaMemsetAsync(degp, 0, N_NODES * sizeof(int));
    cudaMemsetAsync(sump, 0, 4 * HID * sizeof(float));
    cudaMemsetAsync(sqp,  0, 4 * HID * sizeof(float));
    count_deg_kernel<<<(N_EDGES + 255) / 256, 256>>>(ei);
    scan_kernel<<<1, 1024>>>();
    fill_csr_kernel<<<(E2 / 2 + 255) / 256, 256>>>(ei);

    const int GEMM_GRID = (N_NODES + 127) / 128;   // 391
    const int SPMM_GRID = N_NODES / 8;             // 6250

    // ---- layer 1 (IN_F=128 fp32 input, no BN) ----
    gemm_mma_kernel<128, -1, float><<<GEMM_GRID, 256>>>(x, W1, nullptr, hB, nullptr, nullptr);
    spmm_kernel<true><<<SPMM_GRID, 256>>>(hB, hA, b1, nullptr, 1.f, 0.f, 0);
    // ---- layer 2 (BN set 0 fused into GEMM input) ----
    gemm_mma_kernel<64, 0, __half><<<GEMM_GRID, 256>>>(hA, W2, nullptr, hB, g1, be1);
    spmm_kernel<true><<<SPMM_GRID, 256>>>(hB, hA, b2, nullptr, 1.f, 0.f, 1);
    // ---- extra layer 0 (BN set 1) ----
    gemm_mma_kernel<64, 1, __half><<<GEMM_GRID, 256>>>(hA, Wx, nullptr, hB, g2, be2);
    spmm_kernel<true><<<SPMM_GRID, 256>>>(hB, hA, bx, nullptr, 1.f, 0.f, 2);
    // ---- extra layer 1 (BN set 2) ----
    gemm_mma_kernel<64, 2, __half><<<GEMM_GRID, 256>>>(hA, Wx + 64 * 64, nullptr, hB, g3, be3);
    spmm_kernel<true><<<SPMM_GRID, 256>>>(hB, hA, bx + 64, nullptr, 1.f, 0.f, 3);
    // ---- final BN apply (set 3) -> hA normalized, h0 copy ----
    bn_apply_final_kernel<<<(N_NODES * 32) / 256, 256>>>(hA, h0, g3, be3);

    // ---- APPNP: 10 steps, ping-pong hA <-> hB ----
    __half* cur = hA;
    __half* nxt = hB;
    for (int it = 0; it < 10; it++) {
        spmm_kernel<false><<<SPMM_GRID, 256>>>(cur, nxt, nullptr, h0, 0.9f, 0.1f, 0);
        __half* t = cur; cur = nxt; nxt = t;
    }
    // result in hA

    // ---- head: wmma FC + fused log_softmax ----
    fc_mma_logsoftmax_kernel<<<GEMM_GRID, 256>>>(cur, Wfc, bfc, out);
}